// round 15
// baseline (speedup 1.0000x reference)
#include <cuda_runtime.h>
#include <cuda_fp16.h>
#include <cstdint>
#include <math.h>

#define GD 1935       // GATE_DIM
#define OPAD 304      // padded 300 for U/V/P/Q (19*16)
#define KPAD 2048     // padded GATE_DIM for fp16 gemm
#define NPAD 320      // padded 300 cols (attr)
#define P3PAD 336     // fc3 p cols padded
#define F1PAD 320     // fc1t padded dims (320 k x 320 o)

// ------------------------- device scratch (no allocs) -----------------------
__device__ __align__(16) __half g_gf[768 * KPAD];       // gated features fp16
__device__ __align__(16) __half g_attrh[KPAD * NPAD];   // attr fp16 [k][n]
__device__ __align__(16) __half g_fc3t[OPAD * P3PAD];   // [o][p] fp16
__device__ __align__(16) float  g_f [768 * 300];        // k1 partial (z=0)
__device__ __align__(16) float  g_f2[768 * 300];        // k1 partial (z=1)
__device__ __align__(16) float  g_f3[768 * 300];        // k1 partial (z=2)
__device__ __align__(16) float  g_f4[768 * 300];        // k1 partial (z=3)
__device__ __align__(16) __half g_f1ha[F1PAD * F1PAD];  // [d][o] = fc1_w[o][d], fp16
__device__ __align__(16) __half g_f1hb[F1PAD * F1PAD];  // [d][o] = fc1_w[o][300+d]
__device__ __align__(16) __half g_Uh[384 * OPAD];
__device__ __align__(16) __half g_Vh[384 * OPAD];
__device__ __align__(16) __half g_Ph[384 * OPAD];
__device__ __align__(16) __half g_Qh[384 * OPAD];

// ------------------------------ helpers -------------------------------------
__device__ __forceinline__ void ldsm_x4(uint32_t a, uint32_t& r0, uint32_t& r1,
                                        uint32_t& r2, uint32_t& r3) {
    asm volatile("ldmatrix.sync.aligned.m8n8.x4.shared.b16 {%0,%1,%2,%3}, [%4];"
                 : "=r"(r0), "=r"(r1), "=r"(r2), "=r"(r3) : "r"(a));
}
__device__ __forceinline__ void ldsm_x4t(uint32_t a, uint32_t& r0, uint32_t& r1,
                                         uint32_t& r2, uint32_t& r3) {
    asm volatile("ldmatrix.sync.aligned.m8n8.x4.trans.shared.b16 {%0,%1,%2,%3}, [%4];"
                 : "=r"(r0), "=r"(r1), "=r"(r2), "=r"(r3) : "r"(a));
}
__device__ __forceinline__ void ldsm_x2t(uint32_t a, uint32_t& r0, uint32_t& r1) {
    asm volatile("ldmatrix.sync.aligned.m8n8.x2.trans.shared.b16 {%0,%1}, [%2];"
                 : "=r"(r0), "=r"(r1) : "r"(a));
}
__device__ __forceinline__ void mma16816(float* c, const uint32_t* a, uint32_t b0, uint32_t b1) {
    asm volatile(
        "mma.sync.aligned.m16n8k16.row.col.f32.f16.f16.f32 "
        "{%0,%1,%2,%3},{%4,%5,%6,%7},{%8,%9},{%0,%1,%2,%3};"
        : "+f"(c[0]), "+f"(c[1]), "+f"(c[2]), "+f"(c[3])
        : "r"(a[0]), "r"(a[1]), "r"(a[2]), "r"(a[3]), "r"(b0), "r"(b1));
}
__device__ __forceinline__ uint32_t cvta_s(const void* p) {
    uint32_t a;
    asm("{ .reg .u64 t; cvta.to.shared.u64 t, %1; cvt.u32.u64 %0, t; }"
        : "=r"(a) : "l"(p));
    return a;
}
__device__ __forceinline__ void stcs2(float* p, float2 v) {
    asm volatile("st.global.cs.v2.f32 [%0], {%1, %2};" :: "l"(p), "f"(v.x), "f"(v.y)
                 : "memory");
}
__device__ __forceinline__ void cp16(uint32_t dst, const void* src) {
    asm volatile("cp.async.cg.shared.global [%0], [%1], 16;" :: "r"(dst), "l"(src));
}
__device__ __forceinline__ void cp_commit() {
    asm volatile("cp.async.commit_group;" ::: "memory");
}
template <int N> __device__ __forceinline__ void cp_wait() {
    asm volatile("cp.async.wait_group %0;" :: "n"(N) : "memory");
}

// ------------------------------- K0: prep ----------------------------------
__global__ void k0_prep(const float* __restrict__ f1, const float* __restrict__ f2,
                        const float* __restrict__ gate1, const float* __restrict__ gate2,
                        const float* __restrict__ attr,
                        const float* __restrict__ fc3w, const float* __restrict__ fc1w,
                        const float* __restrict__ box1, const float* __restrict__ box2,
                        const float* __restrict__ fc2w, const float* __restrict__ fc2b) {
    int i = blockIdx.x * 256 + threadIdx.x;
    if (i < 768 * KPAD) {
        int r = i >> 11, k = i & (KPAD - 1);
        float v = 0.f;
        if (k < GD) {
            float g = (r < 384) ? gate1[k] : gate2[k];
            float s = 1.f / (1.f + expf(-g));
            v = ((r < 384) ? f1[(size_t)r * GD + k] : f2[(size_t)(r - 384) * GD + k]) * s;
        }
        g_gf[i] = __float2half_rn(v);
    }
    if (i < KPAD * NPAD) {
        int k = i / NPAD, n = i - k * NPAD;
        g_attrh[i] = __float2half_rn((k < GD && n < 300) ? attr[(size_t)k * 300 + n] : 0.f);
    }
    if (i < OPAD * P3PAD) {               // fc3t[o][p] = fc3_w[p][o]
        int o = i / P3PAD, p = i - o * P3PAD;
        g_fc3t[i] = __float2half_rn((o < 300 && p < 300) ? fc3w[p * 300 + o] : 0.f);
    }
    if (i < F1PAD * F1PAD) {              // fc1t fp16, padded 320x320
        int d = i / F1PAD, o = i - d * F1PAD;
        bool ok = (d < 300 && o < 300);
        g_f1ha[i] = __float2half_rn(ok ? fc1w[o * 600 + d] : 0.f);
        g_f1hb[i] = __float2half_rn(ok ? fc1w[o * 600 + 300 + d] : 0.f);
    }
    if (i < 384 * OPAD) {
        int n = i / OPAD, o = i - n * OPAD;
        float pv = 0.f, qv = 0.f;
        if (o < 300) {
#pragma unroll
            for (int j = 0; j < 5; j++) {
                pv += box1[n * 5 + j] * fc2w[o * 10 + j];
                qv += box2[n * 5 + j] * fc2w[o * 10 + 5 + j];
            }
            pv += fc2b[o];
        }
        g_Ph[i] = __float2half_rn(pv);
        g_Qh[i] = __float2half_rn(qv);
    }
}

// ---- K1: partial f = gf @ attrh, fp16 mma, tile 64x64, K-split 4 ----------
__global__ __launch_bounds__(256) void k1_feat() {
    __shared__ __half Af[64 * 72];
    __shared__ __half Bf[64 * 72];
    int tid = threadIdx.x, lane = tid & 31, w = tid >> 5;
    int wm = w >> 1, wn = w & 1;
    int r0 = blockIdx.x * 64, c0 = blockIdx.y * 64;
    int zoff = blockIdx.z * 512;
    float acc[4][4] = {};
    uint32_t sa = cvta_s(Af), sbB = cvta_s(Bf);
    uint32_t aAddr = sa + ((wm * 16 + (lane & 15)) * 72 + (lane >> 4) * 8) * 2;
    uint32_t bAddr = sbB + ((lane & 15) * 72 + wn * 32 + (lane >> 4) * 8) * 2;

    for (int kc = 0; kc < 8; ++kc) {
        int k0 = zoff + kc * 64;
        __syncthreads();
        for (int i = tid; i < 512; i += 256) {
            int r = i >> 3, u = i & 7;
            *(uint4*)(Af + r * 72 + u * 8) =
                *(const uint4*)(g_gf + (size_t)(r0 + r) * KPAD + k0 + u * 8);
        }
        for (int i = tid; i < 512; i += 256) {
            int k = i >> 3, u = i & 7;
            *(uint4*)(Bf + k * 72 + u * 8) =
                *(const uint4*)(g_attrh + (size_t)(k0 + k) * NPAD + c0 + u * 8);
        }
        __syncthreads();
#pragma unroll
        for (int ks = 0; ks < 4; ++ks) {
            uint32_t a[4];
            ldsm_x4(aAddr + ks * 32, a[0], a[1], a[2], a[3]);
            uint32_t b0, b1, b2, b3, d0, d1, d2, d3;
            ldsm_x4t(bAddr + ks * 2304, b0, b1, b2, b3);
            ldsm_x4t(bAddr + ks * 2304 + 32, d0, d1, d2, d3);
            mma16816(acc[0], a, b0, b1);
            mma16816(acc[1], a, b2, b3);
            mma16816(acc[2], a, d0, d1);
            mma16816(acc[3], a, d2, d3);
        }
    }
    float* dst = (blockIdx.z == 0) ? g_f : (blockIdx.z == 1) ? g_f2
                : (blockIdx.z == 2) ? g_f3 : g_f4;
    int rr = r0 + wm * 16 + (lane >> 2);
    int cbase = c0 + wn * 32 + 2 * (lane & 3);
#pragma unroll
    for (int j = 0; j < 4; ++j) {
        int col = cbase + j * 8;
        if (col < 300) {
            *(float2*)&dst[(size_t)rr * 300 + col] = make_float2(acc[j][0], acc[j][1]);
            *(float2*)&dst[(size_t)(rr + 8) * 300 + col] = make_float2(acc[j][2], acc[j][3]);
        }
    }
}

// ---- K2: U/V = (sum of 4 partials) @ fc1t (+fc1_b), fp16 mma, 64x64 -------
__global__ __launch_bounds__(256) void k2_uv(const float* __restrict__ fc1b) {
    __shared__ __half Af[64 * 72];
    __shared__ __half Bf[64 * 72];
    int tid = threadIdx.x, lane = tid & 31, w = tid >> 5;
    int wm = w >> 1, wn = w & 1;
    int c0 = blockIdx.x * 64, r0 = blockIdx.y * 64;
    bool isU = (r0 < 384);
    const __half* Bmat = isU ? g_f1ha : g_f1hb;
    float acc[4][4] = {};
    uint32_t sa = cvta_s(Af), sbB = cvta_s(Bf);
    uint32_t aAddr = sa + ((wm * 16 + (lane & 15)) * 72 + (lane >> 4) * 8) * 2;
    uint32_t bAddr = sbB + ((lane & 15) * 72 + wn * 32 + (lane >> 4) * 8) * 2;

    for (int kc = 0; kc < 5; ++kc) {
        int k0 = kc * 64;
        __syncthreads();
        // stage A: sum 4 fp32 partials -> fp16 (guard k<300)
        for (int i = tid; i < 2048; i += 256) {
            int r = i >> 5, k2i = (i & 31) * 2;
            int gk = k0 + k2i;
            float a0 = 0.f, a1 = 0.f;
            if (gk < 300) {
                size_t off = (size_t)(r0 + r) * 300 + gk;
                float2 x0 = *(const float2*)&g_f[off];
                float2 x1 = *(const float2*)&g_f2[off];
                float2 x2 = *(const float2*)&g_f3[off];
                float2 x3 = *(const float2*)&g_f4[off];
                a0 = x0.x + x1.x + x2.x + x3.x;
                a1 = (gk + 1 < 300) ? (x0.y + x1.y + x2.y + x3.y) : 0.f;
            }
            *(half2*)(Af + r * 72 + k2i) = __floats2half2_rn(a0, a1);
        }
        // stage B: fc1t fp16, padded -> unguarded uint4
        for (int i = tid; i < 512; i += 256) {
            int k = i >> 3, u = i & 7;
            *(uint4*)(Bf + k * 72 + u * 8) =
                *(const uint4*)(Bmat + (size_t)(k0 + k) * F1PAD + c0 + u * 8);
        }
        __syncthreads();
#pragma unroll
        for (int ks = 0; ks < 4; ++ks) {
            uint32_t a[4];
            ldsm_x4(aAddr + ks * 32, a[0], a[1], a[2], a[3]);
            uint32_t b0, b1, b2, b3, d0, d1, d2, d3;
            ldsm_x4t(bAddr + ks * 2304, b0, b1, b2, b3);
            ldsm_x4t(bAddr + ks * 2304 + 32, d0, d1, d2, d3);
            mma16816(acc[0], a, b0, b1);
            mma16816(acc[1], a, b2, b3);
            mma16816(acc[2], a, d0, d1);
            mma16816(acc[3], a, d2, d3);
        }
    }
    __half* dst = isU ? g_Uh : g_Vh;
    int rr = (isU ? r0 : r0 - 384) + wm * 16 + (lane >> 2);
    int cbase = c0 + wn * 32 + 2 * (lane & 3);
#pragma unroll
    for (int j = 0; j < 4; ++j) {
        int col = cbase + j * 8;
        if (col < OPAD) {
            float b0 = 0.f, b1 = 0.f;
            if (isU) {
                if (col < 300) b0 = fc1b[col];
                if (col + 1 < 300) b1 = fc1b[col + 1];
            }
            *(half2*)&dst[(size_t)rr * OPAD + col] =
                __floats2half2_rn(acc[j][0] + b0, acc[j][1] + b1);
            *(half2*)&dst[(size_t)(rr + 8) * OPAD + col] =
                __floats2half2_rn(acc[j][2] + b0, acc[j][3] + b1);
        }
    }
}

// ------------------------------- K3: fused main -----------------------------
// 256 thr (8 warps), 2 CTAs/SM. Warps: 4 row-groups (32 pairs) x 2 col-groups.
// Block tile 128 pairs; p chunks 6x48 + 1x16. K = o, 19x16, pipelined.
// B double-buffered at half-K granularity via cp.async.
constexpr int OFF_A3 = 1536;
constexpr int OFF_B3 = OFF_A3 + 128 * 608;           // 79360
constexpr int BUF0SZ = 160 * 112;                    // 17920
constexpr int K3_SMEM = OFF_B3 + BUF0SZ + 144 * 112; // 113408

__device__ __forceinline__ void k3_stage(uint32_t dst, int rowbase, int nrows,
                                         int p0, int nseg, int tid) {
    for (int i = tid; i < nrows * nseg; i += 256) {
        int row = i / nseg, seg = i - row * nseg;
        cp16(dst + row * 112 + seg * 16,
             g_fc3t + (size_t)(rowbase + row) * P3PAD + p0 + seg * 8);
    }
    cp_commit();
}

template <int NM, int NKS>
__device__ __forceinline__ void k3_comp_half(uint32_t aAddr, uint32_t bAddr,
                                             float (&acc)[2][NM][4]) {
    uint32_t a0[2][4], a1[2][4], bb[2][2 * NM];
    ldsm_x4(aAddr, a0[0][0], a0[0][1], a0[0][2], a0[0][3]);
    ldsm_x4(aAddr + 16 * 608, a1[0][0], a1[0][1], a1[0][2], a1[0][3]);
    if (NM == 3) {
        ldsm_x4t(bAddr, bb[0][0], bb[0][1], bb[0][2], bb[0][3]);
        ldsm_x2t(bAddr + 32, bb[0][4], bb[0][5]);
    } else {
        ldsm_x2t(bAddr, bb[0][0], bb[0][1]);
    }
#pragma unroll
    for (int ks = 0; ks < NKS; ++ks) {
        int cur = ks & 1, nxt = cur ^ 1;
        if (ks < NKS - 1) {
            uint32_t ao = aAddr + (ks + 1) * 32;
            uint32_t bo = bAddr + (ks + 1) * (16 * 112);
            ldsm_x4(ao, a0[nxt][0], a0[nxt][1], a0[nxt][2], a0[nxt][3]);
            ldsm_x4(ao + 16 * 608, a1[nxt][0], a1[nxt][1], a1[nxt][2], a1[nxt][3]);
            if (NM == 3) {
                ldsm_x4t(bo, bb[nxt][0], bb[nxt][1], bb[nxt][2], bb[nxt][3]);
                ldsm_x2t(bo + 32, bb[nxt][4], bb[nxt][5]);
            } else {
                ldsm_x2t(bo, bb[nxt][0], bb[nxt][1]);
            }
        }
#pragma unroll
        for (int t = 0; t < NM; ++t) {
            mma16816(acc[0][t], a0[cur], bb[cur][2 * t], bb[cur][2 * t + 1]);
            mma16816(acc[1][t], a1[cur], bb[cur][2 * t], bb[cur][2 * t + 1]);
        }
    }
}

__global__ __launch_bounds__(256, 2) void k3_main(const float* __restrict__ wloc,
                                                  const float* __restrict__ fc3b,
                                                  float* __restrict__ out) {
    extern __shared__ char smem[];
    float* sbias = (float*)smem;
    char* Asm = smem + OFF_A3;
    char* Bsm = smem + OFF_B3;

    int tid = threadIdx.x, lane = tid & 31, w = tid >> 5;
    int wr = w & 3, wc = w >> 2;
    int n0 = blockIdx.x * 8, m0 = blockIdx.y * 16;

    // phase 1: stage the 48 unique U/V/P/Q rows into Bsm (608B stride)
    for (int i = tid; i < 48 * 38; i += 256) {
        int rr = i / 38, g = i - rr * 38;
        const __half* src;
        if (rr < 8)        src = g_Uh + (size_t)(n0 + rr) * OPAD;
        else if (rr < 24)  src = g_Vh + (size_t)(m0 + rr - 8) * OPAD;
        else if (rr < 32)  src = g_Ph + (size_t)(n0 + rr - 24) * OPAD;
        else               src = g_Qh + (size_t)(m0 + rr - 32) * OPAD;
        *(uint4*)(Bsm + rr * 608 + g * 16) = *(const uint4*)(src + g * 8);
    }
    for (int i = tid; i < 320; i += 256) sbias[i] = (i < 300) ? fc3b[i] : 0.f;

    float l0 = wloc[0], l1 = wloc[1];
    float mx = fmaxf(l0, l1);
    float e0 = expf(l0 - mx), e1 = expf(l1 - mx);
    float w0 = e0 / (e0 + e1), w1 = e1 / (e0 + e1);
    __syncthreads();

    // phase 2: build A tile (vectorized)
    for (int i = tid; i < 128 * 38; i += 256) {
        int pr = i / 38, g = i - pr * 38;
        int ni = pr >> 4, mi = pr & 15;
        uint4 u4 = *(const uint4*)(Bsm + ni * 608 + g * 16);
        uint4 v4 = *(const uint4*)(Bsm + (8 + mi) * 608 + g * 16);
        uint4 p4 = *(const uint4*)(Bsm + (24 + ni) * 608 + g * 16);
        uint4 q4 = *(const uint4*)(Bsm + (32 + mi) * 608 + g * 16);
        uint4 r4;
        const half2* uh = (const half2*)&u4;
        const half2* vh = (const half2*)&v4;
        const half2* ph = (const half2*)&p4;
        const half2* qh = (const half2*)&q4;
        half2* rh = (half2*)&r4;
#pragma unroll
        for (int e = 0; e < 4; ++e) {
            float2 uf = __half22float2(uh[e]);
            float2 vf = __half22float2(vh[e]);
            float2 pf = __half22float2(ph[e]);
            float2 qf = __half22float2(qh[e]);
            float rA = w0 * fmaxf(uf.x + vf.x, 0.f) + w1 * fmaxf(pf.x + qf.x, 0.f);
            float rB = w0 * fmaxf(uf.y + vf.y, 0.f) + w1 * fmaxf(pf.y + qf.y, 0.f);
            rh[e] = __floats2half2_rn(rA, rB);
        }
        uint32_t boff = (uint32_t)pr * 608 +
                        (((uint32_t)g * 16) ^ (((pr >> 2) & 1u) << 4));
        *(uint4*)(Asm + boff) = r4;
    }

    uint32_t sbase = cvta_s(smem);
    int arow = wr * 32 + (lane & 15);
    uint32_t aAddr = sbase + OFF_A3 + (uint32_t)arow * 608 +
                     ((((uint32_t)lane >> 4) << 4) ^ ((((uint32_t)arow >> 2) & 1u) << 4));
    uint32_t b0base = sbase + OFF_B3;
    uint32_t b1base = b0base + BUF0SZ;
    uint32_t b0Addr3 = b0base + (lane & 15) * 112 + wc * 48 + ((lane >> 4) << 4);
    uint32_t b1Addr3 = b0Addr3 + BUF0SZ;
    uint32_t b0Addr1 = b0base + (lane & 15) * 112 + wc * 16;
    uint32_t b1Addr1 = b0Addr1 + BUF0SZ;
    int rbase = lane >> 2, cb = 2 * (lane & 3);

    __syncthreads();
    k3_stage(b0base, 0, 160, 0, 6, tid);
    k3_stage(b1base, 160, 144, 0, 6, tid);

    for (int pc = 0; pc < 7; ++pc) {
        int p0 = pc * 48;
        cp_wait<1>();
        __syncthreads();
        if (pc < 6) {
            float acc[2][3][4] = {};
            k3_comp_half<3, 10>(aAddr, b0Addr3, acc);
            __syncthreads();
            k3_stage(b0base, 0, 160, p0 + 48, (pc == 5) ? 2 : 6, tid);
            cp_wait<1>();
            __syncthreads();
            k3_comp_half<3, 9>(aAddr + 10 * 32, b1Addr3, acc);
            __syncthreads();
            if (pc < 5)      k3_stage(b1base, 160, 144, p0 + 48, 6, tid);
            else             k3_stage(b1base, 160, 144, 288, 2, tid);
#pragma unroll
            for (int i2 = 0; i2 < 2; ++i2) {
                int pr = wr * 32 + i2 * 16 + rbase;
                int ni = pr >> 4, mi = pr & 15;
                size_t ob1 = ((size_t)(n0 + ni) * 384 + (m0 + mi)) * 300;
                int pr2 = pr + 8;
                int ni2 = pr2 >> 4, mi2 = pr2 & 15;
                size_t ob2 = ((size_t)(n0 + ni2) * 384 + (m0 + mi2)) * 300;
#pragma unroll
                for (int j = 0; j < 3; ++j) {
                    int col = p0 + wc * 24 + j * 8 + cb;
                    stcs2(&out[ob1 + col], make_float2(
                        acc[i2][j][0] + sbias[col], acc[i2][j][1] + sbias[col + 1]));
                    stcs2(&out[ob2 + col], make_float2(
                        acc[i2][j][2] + sbias[col], acc[i2][j][3] + sbias[col + 1]));
                }
            }
        } else {
            float acc[2][1][4] = {};
            k3_comp_half<1, 10>(aAddr, b0Addr1, acc);
            cp_wait<0>();
            __syncthreads();
            k3_comp_half<1, 9>(aAddr + 10 * 32, b1Addr1, acc);
#pragma unroll
            for (int i2 = 0; i2 < 2; ++i2) {
                int pr = wr * 32 + i2 * 16 + rbase;
                int ni = pr >> 4, mi = pr & 15;
                size_t ob1 = ((size_t)(n0 + ni) * 384 + (m0 + mi)) * 300;
                int pr2 = pr + 8;
                int ni2 = pr2 >> 4, mi2 = pr2 & 15;
                size_t ob2 = ((size_t)(n0 + ni2) * 384 + (m0 + mi2)) * 300;
                int col = 288 + wc * 8 + cb;
                if (col < 300) {
                    stcs2(&out[ob1 + col], make_float2(
                        acc[i2][0][0] + sbias[col], acc[i2][0][1] + sbias[col + 1]));
                    stcs2(&out[ob2 + col], make_float2(
                        acc[i2][0][2] + sbias[col], acc[i2][0][3] + sbias[col + 1]));
                }
            }
        }
    }
}

// ------------------------------- launch -------------------------------------
extern "C" void kernel_launch(void* const* d_in, const int* in_sizes, int n_in,
                              void* d_out, int out_size) {
    const float* feature1 = (const float*)d_in[0];
    const float* box1     = (const float*)d_in[1];
    const float* feature2 = (const float*)d_in[2];
    const float* box2     = (const float*)d_in[3];
    const float* attr     = (const float*)d_in[4];
    const float* gate1    = (const float*)d_in[5];
    const float* gate2    = (const float*)d_in[6];
    const float* wloc     = (const float*)d_in[7];
    const float* fc1_w    = (const float*)d_in[8];
    const float* fc1_b    = (const float*)d_in[9];
    const float* fc2_w    = (const float*)d_in[10];
    const float* fc2_b    = (const float*)d_in[11];
    const float* fc3_w    = (const float*)d_in[12];
    const float* fc3_b    = (const float*)d_in[13];
    float* out = (float*)d_out;

    static bool attr_set = false;
    if (!attr_set) {
        cudaFuncSetAttribute(k3_main, cudaFuncAttributeMaxDynamicSharedMemorySize, K3_SMEM);
        attr_set = true;
    }

    k0_prep<<<6144, 256>>>(feature1, feature2, gate1, gate2, attr,
                           fc3_w, fc1_w, box1, box2, fc2_w, fc2_b);
    k1_feat<<<dim3(12, 5, 4), 256>>>();
    k2_uv<<<dim3(5, 12), 256>>>(fc1_b);
    k3_main<<<dim3(48, 24), 256, K3_SMEM>>>(wloc, fc3_b, out);
}

// round 16
// speedup vs baseline: 1.0664x; 1.0664x over previous
#include <cuda_runtime.h>
#include <cuda_fp16.h>
#include <cstdint>
#include <math.h>

#define GD 1935       // GATE_DIM
#define OPAD 304      // padded 300 for U/V/P/Q (19*16)
#define KPAD 2048     // padded GATE_DIM for fp16 gemm
#define NPAD 320      // padded 300 cols (attr)
#define P3PAD 336     // fc3 p cols padded

// ------------------------- device scratch (no allocs) -----------------------
__device__ __align__(16) __half g_gf[768 * KPAD];       // gated features fp16
__device__ __align__(16) __half g_attrh[KPAD * NPAD];   // attr fp16 [k][n]
__device__ __align__(16) __half g_fc3t[OPAD * P3PAD];   // [o][p] fp16
__device__ __align__(16) __half g_f [768 * 300];        // k1 partial (z=0), fp16
__device__ __align__(16) __half g_f2[768 * 300];        // k1 partial (z=1)
__device__ __align__(16) __half g_f3[768 * 300];        // k1 partial (z=2)
__device__ __align__(16) __half g_f4[768 * 300];        // k1 partial (z=3)
__device__ __align__(16) float  g_fc1ta[300 * OPAD];    // [d][o] = fc1_w[o][d]
__device__ __align__(16) float  g_fc1tb[300 * OPAD];    // [d][o] = fc1_w[o][300+d]
__device__ __align__(16) __half g_Uh[384 * OPAD];
__device__ __align__(16) __half g_Vh[384 * OPAD];
__device__ __align__(16) __half g_Ph[384 * OPAD];
__device__ __align__(16) __half g_Qh[384 * OPAD];

// ------------------------------ helpers -------------------------------------
__device__ __forceinline__ void ldsm_x4(uint32_t a, uint32_t& r0, uint32_t& r1,
                                        uint32_t& r2, uint32_t& r3) {
    asm volatile("ldmatrix.sync.aligned.m8n8.x4.shared.b16 {%0,%1,%2,%3}, [%4];"
                 : "=r"(r0), "=r"(r1), "=r"(r2), "=r"(r3) : "r"(a));
}
__device__ __forceinline__ void ldsm_x4t(uint32_t a, uint32_t& r0, uint32_t& r1,
                                         uint32_t& r2, uint32_t& r3) {
    asm volatile("ldmatrix.sync.aligned.m8n8.x4.trans.shared.b16 {%0,%1,%2,%3}, [%4];"
                 : "=r"(r0), "=r"(r1), "=r"(r2), "=r"(r3) : "r"(a));
}
__device__ __forceinline__ void ldsm_x2t(uint32_t a, uint32_t& r0, uint32_t& r1) {
    asm volatile("ldmatrix.sync.aligned.m8n8.x2.trans.shared.b16 {%0,%1}, [%2];"
                 : "=r"(r0), "=r"(r1) : "r"(a));
}
__device__ __forceinline__ void mma16816(float* c, const uint32_t* a, uint32_t b0, uint32_t b1) {
    asm volatile(
        "mma.sync.aligned.m16n8k16.row.col.f32.f16.f16.f32 "
        "{%0,%1,%2,%3},{%4,%5,%6,%7},{%8,%9},{%0,%1,%2,%3};"
        : "+f"(c[0]), "+f"(c[1]), "+f"(c[2]), "+f"(c[3])
        : "r"(a[0]), "r"(a[1]), "r"(a[2]), "r"(a[3]), "r"(b0), "r"(b1));
}
__device__ __forceinline__ uint32_t cvta_s(const void* p) {
    uint32_t a;
    asm("{ .reg .u64 t; cvta.to.shared.u64 t, %1; cvt.u32.u64 %0, t; }"
        : "=r"(a) : "l"(p));
    return a;
}
__device__ __forceinline__ void stcs2(float* p, float2 v) {
    asm volatile("st.global.cs.v2.f32 [%0], {%1, %2};" :: "l"(p), "f"(v.x), "f"(v.y)
                 : "memory");
}
__device__ __forceinline__ void cp16(uint32_t dst, const void* src) {
    asm volatile("cp.async.cg.shared.global [%0], [%1], 16;" :: "r"(dst), "l"(src));
}
__device__ __forceinline__ void cp_commit() {
    asm volatile("cp.async.commit_group;" ::: "memory");
}
template <int N> __device__ __forceinline__ void cp_wait() {
    asm volatile("cp.async.wait_group %0;" :: "n"(N) : "memory");
}

// ------------------------------- K0: prep ----------------------------------
__global__ void k0_prep(const float* __restrict__ f1, const float* __restrict__ f2,
                        const float* __restrict__ gate1, const float* __restrict__ gate2,
                        const float* __restrict__ attr,
                        const float* __restrict__ fc3w, const float* __restrict__ fc1w,
                        const float* __restrict__ box1, const float* __restrict__ box2,
                        const float* __restrict__ fc2w, const float* __restrict__ fc2b) {
    int i = blockIdx.x * 256 + threadIdx.x;
    if (i < 768 * KPAD) {
        int r = i >> 11, k = i & (KPAD - 1);
        float v = 0.f;
        if (k < GD) {
            float g = (r < 384) ? gate1[k] : gate2[k];
            float s = 1.f / (1.f + expf(-g));
            v = ((r < 384) ? f1[(size_t)r * GD + k] : f2[(size_t)(r - 384) * GD + k]) * s;
        }
        g_gf[i] = __float2half_rn(v);
    }
    if (i < KPAD * NPAD) {
        int k = i / NPAD, n = i - k * NPAD;
        g_attrh[i] = __float2half_rn((k < GD && n < 300) ? attr[(size_t)k * 300 + n] : 0.f);
    }
    if (i < OPAD * P3PAD) {               // fc3t[o][p] = fc3_w[p][o]
        int o = i / P3PAD, p = i - o * P3PAD;
        g_fc3t[i] = __float2half_rn((o < 300 && p < 300) ? fc3w[p * 300 + o] : 0.f);
    }
    if (i < 300 * OPAD) {
        int d = i / OPAD, o = i - d * OPAD;
        g_fc1ta[i] = (o < 300) ? fc1w[o * 600 + d] : 0.f;
        g_fc1tb[i] = (o < 300) ? fc1w[o * 600 + 300 + d] : 0.f;
    }
    if (i < 384 * OPAD) {
        int n = i / OPAD, o = i - n * OPAD;
        float pv = 0.f, qv = 0.f;
        if (o < 300) {
#pragma unroll
            for (int j = 0; j < 5; j++) {
                pv += box1[n * 5 + j] * fc2w[o * 10 + j];
                qv += box2[n * 5 + j] * fc2w[o * 10 + 5 + j];
            }
            pv += fc2b[o];
        }
        g_Ph[i] = __float2half_rn(pv);
        g_Qh[i] = __float2half_rn(qv);
    }
}

// ---- K1: partial f = gf @ attrh, fp16 mma, tile 64x64, K-split 4 ----------
__global__ __launch_bounds__(256) void k1_feat() {
    __shared__ __half Af[64 * 72];
    __shared__ __half Bf[64 * 72];
    int tid = threadIdx.x, lane = tid & 31, w = tid >> 5;
    int wm = w >> 1, wn = w & 1;
    int r0 = blockIdx.x * 64, c0 = blockIdx.y * 64;
    int zoff = blockIdx.z * 512;
    float acc[4][4] = {};
    uint32_t sa = cvta_s(Af), sbB = cvta_s(Bf);
    uint32_t aAddr = sa + ((wm * 16 + (lane & 15)) * 72 + (lane >> 4) * 8) * 2;
    uint32_t bAddr = sbB + ((lane & 15) * 72 + wn * 32 + (lane >> 4) * 8) * 2;

    for (int kc = 0; kc < 8; ++kc) {
        int k0 = zoff + kc * 64;
        __syncthreads();
        for (int i = tid; i < 512; i += 256) {
            int r = i >> 3, u = i & 7;
            *(uint4*)(Af + r * 72 + u * 8) =
                *(const uint4*)(g_gf + (size_t)(r0 + r) * KPAD + k0 + u * 8);
        }
        for (int i = tid; i < 512; i += 256) {
            int k = i >> 3, u = i & 7;
            *(uint4*)(Bf + k * 72 + u * 8) =
                *(const uint4*)(g_attrh + (size_t)(k0 + k) * NPAD + c0 + u * 8);
        }
        __syncthreads();
#pragma unroll
        for (int ks = 0; ks < 4; ++ks) {
            uint32_t a[4];
            ldsm_x4(aAddr + ks * 32, a[0], a[1], a[2], a[3]);
            uint32_t b0, b1, b2, b3, d0, d1, d2, d3;
            ldsm_x4t(bAddr + ks * 2304, b0, b1, b2, b3);
            ldsm_x4t(bAddr + ks * 2304 + 32, d0, d1, d2, d3);
            mma16816(acc[0], a, b0, b1);
            mma16816(acc[1], a, b2, b3);
            mma16816(acc[2], a, d0, d1);
            mma16816(acc[3], a, d2, d3);
        }
    }
    __half* dst = (blockIdx.z == 0) ? g_f : (blockIdx.z == 1) ? g_f2
                 : (blockIdx.z == 2) ? g_f3 : g_f4;
    int rr = r0 + wm * 16 + (lane >> 2);
    int cbase = c0 + wn * 32 + 2 * (lane & 3);
#pragma unroll
    for (int j = 0; j < 4; ++j) {
        int col = cbase + j * 8;
        if (col < 300) {
            *(half2*)&dst[(size_t)rr * 300 + col] =
                __floats2half2_rn(acc[j][0], acc[j][1]);
            *(half2*)&dst[(size_t)(rr + 8) * 300 + col] =
                __floats2half2_rn(acc[j][2], acc[j][3]);
        }
    }
}

// --------- K2: U/V[384,304] = (sum of 4 fp16 partials) @ fc1t (+fc1_b) -----
__global__ void k2_uv(const float* __restrict__ fc1b) {
    __shared__ float As[32 * 34];
    __shared__ float Bs[32 * 34];
    int tid = threadIdx.x;
    int tx = tid & 15, ty = tid >> 4;
    int r0 = blockIdx.y * 32, c0 = blockIdx.x * 32;
    bool isU = (r0 < 384);
    const float* Bmat = isU ? g_fc1ta : g_fc1tb;
    float a00 = 0.f, a01 = 0.f, a10 = 0.f, a11 = 0.f;
    for (int kt = 0; kt < 10; ++kt) {
        int k0 = kt * 32;
#pragma unroll
        for (int idx = tid; idx < 1024; idx += 256) {
            int r = idx >> 5, k = idx & 31;
            int gk = k0 + k;
            float av = 0.f;
            if (gk < 300) {
                size_t off = (size_t)(r0 + r) * 300 + gk;
                av = __half2float(g_f[off]) + __half2float(g_f2[off]) +
                     __half2float(g_f3[off]) + __half2float(g_f4[off]);
            }
            As[k * 34 + r] = av;
            int kb = idx >> 5, c = idx & 31;
            int gkb = k0 + kb, gc = c0 + c;
            Bs[kb * 34 + c] = (gkb < 300 && gc < OPAD) ? Bmat[gkb * OPAD + gc] : 0.f;
        }
        __syncthreads();
#pragma unroll
        for (int kk = 0; kk < 32; ++kk) {
            float2 a = *(const float2*)&As[kk * 34 + ty * 2];
            float2 b = *(const float2*)&Bs[kk * 34 + tx * 2];
            a00 += a.x * b.x; a01 += a.x * b.y;
            a10 += a.y * b.x; a11 += a.y * b.y;
        }
        __syncthreads();
    }
    int r = r0 + ty * 2, c = c0 + tx * 2;
    if (c < OPAD) {
        float b0 = 0.f, b1 = 0.f;
        if (isU) {
            if (c < 300) b0 = fc1b[c];
            if (c + 1 < 300) b1 = fc1b[c + 1];
        }
        __half* dst = isU ? g_Uh : g_Vh;
        int rr = isU ? r : r - 384;
        *(half2*)&dst[rr * OPAD + c] = __floats2half2_rn(a00 + b0, a01 + b1);
        *(half2*)&dst[(rr + 1) * OPAD + c] = __floats2half2_rn(a10 + b0, a11 + b1);
    }
}

// ------------------------------- K3: fused main -----------------------------
// 256 thr (8 warps), 2 CTAs/SM. Warps: 4 row-groups (32 pairs) x 2 col-groups.
// Block tile 128 pairs; p chunks 6x48 + 1x16. K = o, 19x16, pipelined.
// B double-buffered at half-K granularity via cp.async.
constexpr int OFF_A3 = 1536;
constexpr int OFF_B3 = OFF_A3 + 128 * 608;           // 79360
constexpr int BUF0SZ = 160 * 112;                    // 17920
constexpr int K3_SMEM = OFF_B3 + BUF0SZ + 144 * 112; // 113408

__device__ __forceinline__ void k3_stage(uint32_t dst, int rowbase, int nrows,
                                         int p0, int nseg, int tid) {
    for (int i = tid; i < nrows * nseg; i += 256) {
        int row = i / nseg, seg = i - row * nseg;
        cp16(dst + row * 112 + seg * 16,
             g_fc3t + (size_t)(rowbase + row) * P3PAD + p0 + seg * 8);
    }
    cp_commit();
}

template <int NM, int NKS>
__device__ __forceinline__ void k3_comp_half(uint32_t aAddr, uint32_t bAddr,
                                             float (&acc)[2][NM][4]) {
    uint32_t a0[2][4], a1[2][4], bb[2][2 * NM];
    ldsm_x4(aAddr, a0[0][0], a0[0][1], a0[0][2], a0[0][3]);
    ldsm_x4(aAddr + 16 * 608, a1[0][0], a1[0][1], a1[0][2], a1[0][3]);
    if (NM == 3) {
        ldsm_x4t(bAddr, bb[0][0], bb[0][1], bb[0][2], bb[0][3]);
        ldsm_x2t(bAddr + 32, bb[0][4], bb[0][5]);
    } else {
        ldsm_x2t(bAddr, bb[0][0], bb[0][1]);
    }
#pragma unroll
    for (int ks = 0; ks < NKS; ++ks) {
        int cur = ks & 1, nxt = cur ^ 1;
        if (ks < NKS - 1) {
            uint32_t ao = aAddr + (ks + 1) * 32;
            uint32_t bo = bAddr + (ks + 1) * (16 * 112);
            ldsm_x4(ao, a0[nxt][0], a0[nxt][1], a0[nxt][2], a0[nxt][3]);
            ldsm_x4(ao + 16 * 608, a1[nxt][0], a1[nxt][1], a1[nxt][2], a1[nxt][3]);
            if (NM == 3) {
                ldsm_x4t(bo, bb[nxt][0], bb[nxt][1], bb[nxt][2], bb[nxt][3]);
                ldsm_x2t(bo + 32, bb[nxt][4], bb[nxt][5]);
            } else {
                ldsm_x2t(bo, bb[nxt][0], bb[nxt][1]);
            }
        }
#pragma unroll
        for (int t = 0; t < NM; ++t) {
            mma16816(acc[0][t], a0[cur], bb[cur][2 * t], bb[cur][2 * t + 1]);
            mma16816(acc[1][t], a1[cur], bb[cur][2 * t], bb[cur][2 * t + 1]);
        }
    }
}

__global__ __launch_bounds__(256, 2) void k3_main(const float* __restrict__ wloc,
                                                  const float* __restrict__ fc3b,
                                                  float* __restrict__ out) {
    extern __shared__ char smem[];
    float* sbias = (float*)smem;
    char* Asm = smem + OFF_A3;
    char* Bsm = smem + OFF_B3;

    int tid = threadIdx.x, lane = tid & 31, w = tid >> 5;
    int wr = w & 3, wc = w >> 2;
    int n0 = blockIdx.x * 8, m0 = blockIdx.y * 16;

    // phase 1: stage the 48 unique U/V/P/Q rows into Bsm (608B stride)
    for (int i = tid; i < 48 * 38; i += 256) {
        int rr = i / 38, g = i - rr * 38;
        const __half* src;
        if (rr < 8)        src = g_Uh + (size_t)(n0 + rr) * OPAD;
        else if (rr < 24)  src = g_Vh + (size_t)(m0 + rr - 8) * OPAD;
        else if (rr < 32)  src = g_Ph + (size_t)(n0 + rr - 24) * OPAD;
        else               src = g_Qh + (size_t)(m0 + rr - 32) * OPAD;
        *(uint4*)(Bsm + rr * 608 + g * 16) = *(const uint4*)(src + g * 8);
    }
    for (int i = tid; i < 320; i += 256) sbias[i] = (i < 300) ? fc3b[i] : 0.f;

    float l0 = wloc[0], l1 = wloc[1];
    float mx = fmaxf(l0, l1);
    float e0 = expf(l0 - mx), e1 = expf(l1 - mx);
    float w0 = e0 / (e0 + e1), w1 = e1 / (e0 + e1);
    __syncthreads();

    // phase 2: build A tile (vectorized)
    for (int i = tid; i < 128 * 38; i += 256) {
        int pr = i / 38, g = i - pr * 38;
        int ni = pr >> 4, mi = pr & 15;
        uint4 u4 = *(const uint4*)(Bsm + ni * 608 + g * 16);
        uint4 v4 = *(const uint4*)(Bsm + (8 + mi) * 608 + g * 16);
        uint4 p4 = *(const uint4*)(Bsm + (24 + ni) * 608 + g * 16);
        uint4 q4 = *(const uint4*)(Bsm + (32 + mi) * 608 + g * 16);
        uint4 r4;
        const half2* uh = (const half2*)&u4;
        const half2* vh = (const half2*)&v4;
        const half2* ph = (const half2*)&p4;
        const half2* qh = (const half2*)&q4;
        half2* rh = (half2*)&r4;
#pragma unroll
        for (int e = 0; e < 4; ++e) {
            float2 uf = __half22float2(uh[e]);
            float2 vf = __half22float2(vh[e]);
            float2 pf = __half22float2(ph[e]);
            float2 qf = __half22float2(qh[e]);
            float rA = w0 * fmaxf(uf.x + vf.x, 0.f) + w1 * fmaxf(pf.x + qf.x, 0.f);
            float rB = w0 * fmaxf(uf.y + vf.y, 0.f) + w1 * fmaxf(pf.y + qf.y, 0.f);
            rh[e] = __floats2half2_rn(rA, rB);
        }
        uint32_t boff = (uint32_t)pr * 608 +
                        (((uint32_t)g * 16) ^ (((pr >> 2) & 1u) << 4));
        *(uint4*)(Asm + boff) = r4;
    }

    uint32_t sbase = cvta_s(smem);
    int arow = wr * 32 + (lane & 15);
    uint32_t aAddr = sbase + OFF_A3 + (uint32_t)arow * 608 +
                     ((((uint32_t)lane >> 4) << 4) ^ ((((uint32_t)arow >> 2) & 1u) << 4));
    uint32_t b0base = sbase + OFF_B3;
    uint32_t b1base = b0base + BUF0SZ;
    uint32_t b0Addr3 = b0base + (lane & 15) * 112 + wc * 48 + ((lane >> 4) << 4);
    uint32_t b1Addr3 = b0Addr3 + BUF0SZ;
    uint32_t b0Addr1 = b0base + (lane & 15) * 112 + wc * 16;
    uint32_t b1Addr1 = b0Addr1 + BUF0SZ;
    int rbase = lane >> 2, cb = 2 * (lane & 3);

    __syncthreads();
    k3_stage(b0base, 0, 160, 0, 6, tid);
    k3_stage(b1base, 160, 144, 0, 6, tid);

    for (int pc = 0; pc < 7; ++pc) {
        int p0 = pc * 48;
        cp_wait<1>();
        __syncthreads();
        if (pc < 6) {
            float acc[2][3][4] = {};
            k3_comp_half<3, 10>(aAddr, b0Addr3, acc);
            __syncthreads();
            k3_stage(b0base, 0, 160, p0 + 48, (pc == 5) ? 2 : 6, tid);
            cp_wait<1>();
            __syncthreads();
            k3_comp_half<3, 9>(aAddr + 10 * 32, b1Addr3, acc);
            __syncthreads();
            if (pc < 5)      k3_stage(b1base, 160, 144, p0 + 48, 6, tid);
            else             k3_stage(b1base, 160, 144, 288, 2, tid);
#pragma unroll
            for (int i2 = 0; i2 < 2; ++i2) {
                int pr = wr * 32 + i2 * 16 + rbase;
                int ni = pr >> 4, mi = pr & 15;
                size_t ob1 = ((size_t)(n0 + ni) * 384 + (m0 + mi)) * 300;
                int pr2 = pr + 8;
                int ni2 = pr2 >> 4, mi2 = pr2 & 15;
                size_t ob2 = ((size_t)(n0 + ni2) * 384 + (m0 + mi2)) * 300;
#pragma unroll
                for (int j = 0; j < 3; ++j) {
                    int col = p0 + wc * 24 + j * 8 + cb;
                    stcs2(&out[ob1 + col], make_float2(
                        acc[i2][j][0] + sbias[col], acc[i2][j][1] + sbias[col + 1]));
                    stcs2(&out[ob2 + col], make_float2(
                        acc[i2][j][2] + sbias[col], acc[i2][j][3] + sbias[col + 1]));
                }
            }
        } else {
            float acc[2][1][4] = {};
            k3_comp_half<1, 10>(aAddr, b0Addr1, acc);
            cp_wait<0>();
            __syncthreads();
            k3_comp_half<1, 9>(aAddr + 10 * 32, b1Addr1, acc);
#pragma unroll
            for (int i2 = 0; i2 < 2; ++i2) {
                int pr = wr * 32 + i2 * 16 + rbase;
                int ni = pr >> 4, mi = pr & 15;
                size_t ob1 = ((size_t)(n0 + ni) * 384 + (m0 + mi)) * 300;
                int pr2 = pr + 8;
                int ni2 = pr2 >> 4, mi2 = pr2 & 15;
                size_t ob2 = ((size_t)(n0 + ni2) * 384 + (m0 + mi2)) * 300;
                int col = 288 + wc * 8 + cb;
                if (col < 300) {
                    stcs2(&out[ob1 + col], make_float2(
                        acc[i2][0][0] + sbias[col], acc[i2][0][1] + sbias[col + 1]));
                    stcs2(&out[ob2 + col], make_float2(
                        acc[i2][0][2] + sbias[col], acc[i2][0][3] + sbias[col + 1]));
                }
            }
        }
    }
}

// ------------------------------- launch -------------------------------------
extern "C" void kernel_launch(void* const* d_in, const int* in_sizes, int n_in,
                              void* d_out, int out_size) {
    const float* feature1 = (const float*)d_in[0];
    const float* box1     = (const float*)d_in[1];
    const float* feature2 = (const float*)d_in[2];
    const float* box2     = (const float*)d_in[3];
    const float* attr     = (const float*)d_in[4];
    const float* gate1    = (const float*)d_in[5];
    const float* gate2    = (const float*)d_in[6];
    const float* wloc     = (const float*)d_in[7];
    const float* fc1_w    = (const float*)d_in[8];
    const float* fc1_b    = (const float*)d_in[9];
    const float* fc2_w    = (const float*)d_in[10];
    const float* fc2_b    = (const float*)d_in[11];
    const float* fc3_w    = (const float*)d_in[12];
    const float* fc3_b    = (const float*)d_in[13];
    float* out = (float*)d_out;

    static bool attr_set = false;
    if (!attr_set) {
        cudaFuncSetAttribute(k3_main, cudaFuncAttributeMaxDynamicSharedMemorySize, K3_SMEM);
        attr_set = true;
    }

    k0_prep<<<6144, 256>>>(feature1, feature2, gate1, gate2, attr,
                           fc3_w, fc1_w, box1, box2, fc2_w, fc2_b);
    k1_feat<<<dim3(12, 5, 4), 256>>>();
    k2_uv<<<dim3(10, 24), 256>>>(fc1_b);
    k3_main<<<dim3(48, 24), 256, K3_SMEM>>>(wloc, fc3_b, out);
}